// round 7
// baseline (speedup 1.0000x reference)
#include <cuda_runtime.h>
#include <cuda_bf16.h>
#include <stdint.h>

#define MAX_N 100000
#define MAX_E 1000000
#define D 64
#define NB_MAX 1024          // MAX_N/256 = 391 <= 1024

// Scratch (device globals; no allocation allowed)
__device__ float g_deg[MAX_N];
__device__ float g_dis[MAX_N];
__device__ int   g_cnt[MAX_N];
__device__ int   g_base[MAX_N];
__device__ int   g_pos[MAX_N];
__device__ int   g_bsum[NB_MAX];
__device__ __align__(16) float  g_y[(size_t)MAX_N * D];     // y = x @ W^T
__device__ __align__(16) float2 g_epack[MAX_E];             // (col, norm) CSR-ordered
__device__ int g_is64;

__device__ __forceinline__ int edge_idx(const void* ei, size_t pos, int is64) {
    return is64 ? (int)((const long long*)ei)[pos] : ((const int*)ei)[pos];
}

// ---------------------------------------------------------------------------
// 1) fused: init deg=1/cnt=0 (all blocks) + dtype detect (block 0)
__global__ void k_pre(const void* __restrict__ ei, int E, int n) {
    int i = blockIdx.x * blockDim.x + threadIdx.x;
    if (i < n) { g_deg[i] = 1.0f; g_cnt[i] = 0; }
    if (blockIdx.x == 0) {
        __shared__ int ok;
        if (threadIdx.x == 0) ok = 1;
        __syncthreads();
        const long long* p = (const long long*)ei;
        int scan = 2 * E < 2048 ? 2 * E : 2048;
        for (int t = threadIdx.x; t < scan; t += blockDim.x) {
            long long v = p[t];
            if (v < 0 || v >= (long long)n) ok = 0;   // benign race
        }
        __syncthreads();
        if (threadIdx.x == 0) g_is64 = ok;
    }
}

// 2) per-edge: deg[row] += ew, cnt[row] += 1
__global__ void k_acc(const void* __restrict__ ei,
                      const float* __restrict__ ew, int E, int n) {
    int e = blockIdx.x * blockDim.x + threadIdx.x;
    if (e >= E) return;
    int is64 = g_is64;
    int r = edge_idx(ei, e, is64);
    if ((unsigned)r < (unsigned)n) {
        atomicAdd(&g_deg[r], ew[e]);
        atomicAdd(&g_cnt[r], 1);
    }
}

// 3) fused: dis = rsqrt(deg) + per-block cnt sums
__global__ void k_dis_scan1(int n) {
    __shared__ int sm[256];
    int i = blockIdx.x * 256 + threadIdx.x;
    int c = 0;
    if (i < n) { g_dis[i] = rsqrtf(g_deg[i]); c = g_cnt[i]; }
    sm[threadIdx.x] = c;
    __syncthreads();
    for (int s = 128; s > 0; s >>= 1) {
        if (threadIdx.x < s) sm[threadIdx.x] += sm[threadIdx.x + s];
        __syncthreads();
    }
    if (threadIdx.x == 0) g_bsum[blockIdx.x] = sm[0];
}

// 4) exclusive scan of block sums (single block, nb <= 1024)
__global__ void k_scan2(int nb) {
    __shared__ int sm[NB_MAX];
    int t = threadIdx.x;
    int orig = (t < nb) ? g_bsum[t] : 0;
    sm[t] = orig;
    __syncthreads();
    for (int off = 1; off < NB_MAX; off <<= 1) {
        int v = (t >= off) ? sm[t - off] : 0;
        __syncthreads();
        sm[t] += v;
        __syncthreads();
    }
    if (t < nb) g_bsum[t] = sm[t] - orig;
}

// 5) per-node exclusive base = blockbase + within-block exclusive scan
__global__ void k_scan3(int n) {
    __shared__ int sm[256];
    int i = blockIdx.x * 256 + threadIdx.x;
    int c = (i < n) ? g_cnt[i] : 0;
    sm[threadIdx.x] = c;
    __syncthreads();
    for (int off = 1; off < 256; off <<= 1) {
        int v = (threadIdx.x >= off) ? sm[threadIdx.x - off] : 0;
        __syncthreads();
        sm[threadIdx.x] += v;
        __syncthreads();
    }
    if (i < n) {
        int b = g_bsum[blockIdx.x] + sm[threadIdx.x] - c;
        g_base[i] = b;
        g_pos[i]  = b;
    }
}

// 6) y = x @ W^T.  W is [D_OUT, D_IN] row-major.
__global__ void k_gemm(const float* __restrict__ x,
                       const float* __restrict__ W, int n) {
    __shared__ float sWt[D * D];   // sWt[k*64+j] = W[j*64+k]
    __shared__ float sx[4][D];
    for (int i = threadIdx.x; i < D * D; i += 256) {
        int j = i >> 6, k = i & 63;
        sWt[k * D + j] = W[i];
    }
    __syncthreads();
    int j  = threadIdx.x & 63;
    int rl = threadIdx.x >> 6;
    int base = blockIdx.x * 32;
    for (int rr = 0; rr < 32; rr += 4) {
        int r = base + rr + rl;
        __syncthreads();
        if (r < n) sx[rl][j] = x[(size_t)r * D + j];
        __syncthreads();
        if (r < n) {
            float acc = 0.0f;
            #pragma unroll
            for (int k = 0; k < D; k++)
                acc = fmaf(sx[rl][k], sWt[k * D + j], acc);
            g_y[(size_t)r * D + j] = acc;
        }
    }
}

// 7) reorder edges into CSR: g_epack[pos[row]++] = (col, norm)
__global__ void k_reorder(const void* __restrict__ ei,
                          const float* __restrict__ ew, int E, int n) {
    int e = blockIdx.x * blockDim.x + threadIdx.x;
    if (e >= E) return;
    int is64 = g_is64;
    int r  = edge_idx(ei, e, is64);
    int cl = edge_idx(ei, (size_t)E + e, is64);
    if ((unsigned)r >= (unsigned)n || (unsigned)cl >= (unsigned)n) return;
    float nm = g_dis[r] * ew[e] * g_dis[cl];
    int p = atomicAdd(&g_pos[r], 1);
    g_epack[p] = make_float2(__int_as_float(cl), nm);
}

// 8) gather: one warp per node; lane owns 2 output floats.
//    Unrolled x4: 4 independent epack loads then 4 independent y loads -> MLP~4.
__global__ void k_gather(const float* __restrict__ bias,
                         float* __restrict__ out, int n) {
    int warp = (blockIdx.x * blockDim.x + threadIdx.x) >> 5;
    int lane = threadIdx.x & 31;
    if (warp >= n) return;
    int node = warp;
    int j = lane << 1;
    float s = g_dis[node];
    float2 yv = *(const float2*)&g_y[(size_t)node * D + j];
    float a0 = bias[j]     + yv.x * s * s;
    float a1 = bias[j + 1] + yv.y * s * s;
    int p   = g_base[node];
    int end = p + g_cnt[node];
    for (; p + 4 <= end; p += 4) {
        float2 pk0 = g_epack[p];
        float2 pk1 = g_epack[p + 1];
        float2 pk2 = g_epack[p + 2];
        float2 pk3 = g_epack[p + 3];
        const float2 v0 = *(const float2*)&g_y[(size_t)__float_as_int(pk0.x) * D + j];
        const float2 v1 = *(const float2*)&g_y[(size_t)__float_as_int(pk1.x) * D + j];
        const float2 v2 = *(const float2*)&g_y[(size_t)__float_as_int(pk2.x) * D + j];
        const float2 v3 = *(const float2*)&g_y[(size_t)__float_as_int(pk3.x) * D + j];
        a0 = fmaf(v0.x, pk0.y, a0);  a1 = fmaf(v0.y, pk0.y, a1);
        a0 = fmaf(v1.x, pk1.y, a0);  a1 = fmaf(v1.y, pk1.y, a1);
        a0 = fmaf(v2.x, pk2.y, a0);  a1 = fmaf(v2.y, pk2.y, a1);
        a0 = fmaf(v3.x, pk3.y, a0);  a1 = fmaf(v3.y, pk3.y, a1);
    }
    for (; p < end; p++) {
        float2 pk = g_epack[p];
        const float2 v = *(const float2*)&g_y[(size_t)__float_as_int(pk.x) * D + j];
        a0 = fmaf(v.x, pk.y, a0);
        a1 = fmaf(v.y, pk.y, a1);
    }
    *(float2*)&out[(size_t)node * D + j] = make_float2(a0, a1);
}

// ---------------------------------------------------------------------------
extern "C" void kernel_launch(void* const* d_in, const int* in_sizes, int n_in,
                              void* d_out, int out_size) {
    const float* x    = (const float*)d_in[0];   // [N,64] f32
    const void*  ei   = d_in[1];                 // [2,E] i64 or i32
    const float* ew   = (const float*)d_in[2];   // [E]   f32
    const float* W    = (const float*)d_in[3];   // [64,64] f32
    const float* bias = (const float*)d_in[4];   // [64]  f32
    float*       out  = (float*)d_out;           // [N,64] f32

    int N = in_sizes[0] / D;
    int E = in_sizes[1] / 2;
    if (N > MAX_N) N = MAX_N;
    if (E > MAX_E) E = MAX_E;
    int nb = (N + 255) / 256;

    const int B = 256;
    k_pre      <<<nb, B>>>(ei, E, N);
    k_acc      <<<(E + B - 1) / B, B>>>(ei, ew, E, N);
    k_dis_scan1<<<nb, B>>>(N);
    k_scan2    <<<1, NB_MAX>>>(nb);
    k_scan3    <<<nb, B>>>(N);
    k_gemm     <<<(N + 31) / 32, 256>>>(x, W, N);
    k_reorder  <<<(E + B - 1) / B, B>>>(ei, ew, E, N);
    long long gth = (long long)N * 32;
    k_gather   <<<(unsigned)((gth + B - 1) / B), B>>>(bias, out, N);
}

// round 12
// speedup vs baseline: 1.0683x; 1.0683x over previous
#include <cuda_runtime.h>
#include <cuda_bf16.h>
#include <stdint.h>

#define MAX_N 100000
#define MAX_E 1000000
#define D 64
#define GRID 592          // 148 SMs * 4 CTAs, all co-resident
#define BLK 256
#define NWARPS (GRID * BLK / 32)

// Scratch (device globals; no allocation allowed)
__device__ float g_deg[MAX_N];
__device__ float g_dis[MAX_N];
__device__ int   g_cnt[MAX_N];
__device__ int   g_base[MAX_N];
__device__ int   g_pos[MAX_N];
__device__ int   g_bsum[(MAX_N + BLK - 1) / BLK];
__device__ __align__(16) float  g_y[(size_t)MAX_N * D];     // y = x @ W^T
__device__ __align__(16) float2 g_epack[MAX_E];             // (col, norm) CSR-ordered
__device__ int g_is64;

// software grid barrier (all GRID blocks resident by construction)
__device__ int g_barArrive = 0;
__device__ int g_barGen    = 0;

__device__ __forceinline__ void gbar() {
    __syncthreads();
    if (threadIdx.x == 0) {
        __threadfence();
        int gen = *(volatile int*)&g_barGen;
        if (atomicAdd(&g_barArrive, 1) == GRID - 1) {
            g_barArrive = 0;
            __threadfence();
            atomicAdd(&g_barGen, 1);
        } else {
            while (*(volatile int*)&g_barGen == gen) __nanosleep(64);
        }
    }
    __syncthreads();
}

__device__ __forceinline__ int edge_idx(const void* ei, size_t pos, int is64) {
    return is64 ? (int)((const long long*)ei)[pos] : ((const int*)ei)[pos];
}

__global__ void __launch_bounds__(BLK, 4)
k_gcn(const float* __restrict__ x, const void* __restrict__ ei,
      const float* __restrict__ ew, const float* __restrict__ W,
      const float* __restrict__ bias, float* __restrict__ out,
      int n, int E) {
    __shared__ float sWt[D * D];
    __shared__ float sx[4][D];
    __shared__ int   sm[BLK];

    const int tid = threadIdx.x;
    const int bid = blockIdx.x;
    const int gt  = bid * BLK + tid;
    const int nb  = (n + BLK - 1) / BLK;

    // ---- P1: init deg=1 / cnt=0 ; block 0 sniffs edge_index dtype ----
    for (int i = gt; i < n; i += GRID * BLK) { g_deg[i] = 1.0f; g_cnt[i] = 0; }
    if (bid == 0) {
        if (tid == 0) sm[0] = 1;
        __syncthreads();
        const long long* p = (const long long*)ei;
        int scan = 2 * E < 2048 ? 2 * E : 2048;
        for (int t = tid; t < scan; t += BLK) {
            long long v = p[t];
            if (v < 0 || v >= (long long)n) sm[0] = 0;   // benign race
        }
        __syncthreads();
        if (tid == 0) g_is64 = sm[0];
    }
    gbar();

    // ---- P2: edge deg/cnt atomics + GEMM (independent, fused phase) ----
    {
        const int is64 = g_is64;
        for (int e = gt; e < E; e += GRID * BLK) {
            int r = edge_idx(ei, e, is64);
            if ((unsigned)r < (unsigned)n) {
                atomicAdd(&g_deg[r], ew[e]);
                atomicAdd(&g_cnt[r], 1);
            }
        }
        // GEMM: y = x @ W^T,  W [D_OUT, D_IN] row-major
        for (int i = tid; i < D * D; i += BLK) {
            int j = i >> 6, k = i & 63;
            sWt[k * D + j] = W[i];
        }
        __syncthreads();
        int j  = tid & 63;
        int rl = tid >> 6;
        int ntiles = (n + 31) / 32;
        for (int t = bid; t < ntiles; t += GRID) {
            int base = t * 32;
            for (int rr = 0; rr < 32; rr += 4) {
                int r = base + rr + rl;
                __syncthreads();
                if (r < n) sx[rl][j] = x[(size_t)r * D + j];
                __syncthreads();
                if (r < n) {
                    float acc = 0.0f;
                    #pragma unroll
                    for (int k = 0; k < D; k++)
                        acc = fmaf(sx[rl][k], sWt[k * D + j], acc);
                    g_y[(size_t)r * D + j] = acc;
                }
            }
        }
    }
    gbar();

    // ---- P3: dis = rsqrt(deg) + block-local inclusive scan of cnt ----
    int local_excl = 0, myc = 0;
    if (bid < nb) {
        int i = bid * BLK + tid;
        myc = (i < n) ? g_cnt[i] : 0;
        if (i < n) g_dis[i] = rsqrtf(g_deg[i]);
        sm[tid] = myc;
        __syncthreads();
        for (int off = 1; off < BLK; off <<= 1) {
            int v = (tid >= off) ? sm[tid - off] : 0;
            __syncthreads();
            sm[tid] += v;
            __syncthreads();
        }
        local_excl = sm[tid] - myc;          // stays in register across gbar
        if (tid == 0) g_bsum[bid] = sm[BLK - 1];
    }
    gbar();

    // ---- P4: cross-block exclusive offset + write base/pos ----
    if (bid < nb) {
        int acc = 0;
        for (int t = tid; t < bid; t += BLK) acc += g_bsum[t];
        sm[tid] = acc;
        __syncthreads();
        for (int s = BLK / 2; s > 0; s >>= 1) {
            if (tid < s) sm[tid] += sm[tid + s];
            __syncthreads();
        }
        int off = sm[0];
        int i = bid * BLK + tid;
        if (i < n) {
            int b = off + local_excl;
            g_base[i] = b;
            g_pos[i]  = b;
        }
    }
    gbar();

    // ---- P5: reorder edges into CSR: epack[pos[row]++] = (col, norm) ----
    {
        const int is64 = g_is64;
        for (int e = gt; e < E; e += GRID * BLK) {
            int r  = edge_idx(ei, e, is64);
            int cl = edge_idx(ei, (size_t)E + e, is64);
            if ((unsigned)r >= (unsigned)n || (unsigned)cl >= (unsigned)n) continue;
            float nm = g_dis[r] * ew[e] * g_dis[cl];
            int p = atomicAdd(&g_pos[r], 1);
            g_epack[p] = make_float2(__int_as_float(cl), nm);
        }
    }
    gbar();

    // ---- P6: gather, warp per node; lane owns float2 of output row ----
    {
        int gw   = gt >> 5;
        int lane = tid & 31;
        int j = lane << 1;
        for (int node = gw; node < n; node += NWARPS) {
            float s = g_dis[node];
            float2 yv = *(const float2*)&g_y[(size_t)node * D + j];
            float a0 = bias[j]     + yv.x * s * s;
            float a1 = bias[j + 1] + yv.y * s * s;
            int p   = g_base[node];
            int end = p + g_cnt[node];
            for (; p + 4 <= end; p += 4) {
                float2 pk0 = g_epack[p];
                float2 pk1 = g_epack[p + 1];
                float2 pk2 = g_epack[p + 2];
                float2 pk3 = g_epack[p + 3];
                const float2 v0 = *(const float2*)&g_y[(size_t)__float_as_int(pk0.x) * D + j];
                const float2 v1 = *(const float2*)&g_y[(size_t)__float_as_int(pk1.x) * D + j];
                const float2 v2 = *(const float2*)&g_y[(size_t)__float_as_int(pk2.x) * D + j];
                const float2 v3 = *(const float2*)&g_y[(size_t)__float_as_int(pk3.x) * D + j];
                a0 = fmaf(v0.x, pk0.y, a0);  a1 = fmaf(v0.y, pk0.y, a1);
                a0 = fmaf(v1.x, pk1.y, a0);  a1 = fmaf(v1.y, pk1.y, a1);
                a0 = fmaf(v2.x, pk2.y, a0);  a1 = fmaf(v2.y, pk2.y, a1);
                a0 = fmaf(v3.x, pk3.y, a0);  a1 = fmaf(v3.y, pk3.y, a1);
            }
            for (; p < end; p++) {
                float2 pk = g_epack[p];
                const float2 v = *(const float2*)&g_y[(size_t)__float_as_int(pk.x) * D + j];
                a0 = fmaf(v.x, pk.y, a0);
                a1 = fmaf(v.y, pk.y, a1);
            }
            *(float2*)&out[(size_t)node * D + j] = make_float2(a0, a1);
        }
    }
}

// ---------------------------------------------------------------------------
extern "C" void kernel_launch(void* const* d_in, const int* in_sizes, int n_in,
                              void* d_out, int out_size) {
    const float* x    = (const float*)d_in[0];   // [N,64] f32
    const void*  ei   = d_in[1];                 // [2,E] i64 or i32
    const float* ew   = (const float*)d_in[2];   // [E]   f32
    const float* W    = (const float*)d_in[3];   // [64,64] f32
    const float* bias = (const float*)d_in[4];   // [64]  f32
    float*       out  = (float*)d_out;           // [N,64] f32

    int N = in_sizes[0] / D;
    int E = in_sizes[1] / 2;
    if (N > MAX_N) N = MAX_N;
    if (E > MAX_E) E = MAX_E;

    k_gcn<<<GRID, BLK>>>(x, ei, ew, W, bias, out, N, E);
}

// round 14
// speedup vs baseline: 1.5551x; 1.4557x over previous
#include <cuda_runtime.h>
#include <cuda_bf16.h>
#include <stdint.h>

#define MAX_N 100000
#define MAX_E 1000000
#define D 64
#define GRID 592          // 148 SMs * 4 CTAs, all co-resident
#define BLK 256
#define NWARPS (GRID * BLK / 32)
#define XPAD 68           // multiple of 4 -> 16B-aligned float4 rows in sxT

// Scratch (device globals; no allocation allowed)
__device__ float g_deg[MAX_N];
__device__ float g_dis[MAX_N];
__device__ int   g_cnt[MAX_N];
__device__ int   g_base[MAX_N];
__device__ int   g_pos[MAX_N];
__device__ int   g_bsum[(MAX_N + BLK - 1) / BLK];
__device__ __align__(16) float  g_y[(size_t)MAX_N * D];     // y = x @ W^T
__device__ __align__(16) float2 g_epack[MAX_E];             // (col, norm) CSR-ordered
__device__ int g_is64;

// software grid barrier (all GRID blocks resident by construction)
__device__ int g_barArrive = 0;
__device__ int g_barGen    = 0;

__device__ __forceinline__ void gbar() {
    __syncthreads();
    if (threadIdx.x == 0) {
        __threadfence();
        int gen = *(volatile int*)&g_barGen;
        if (atomicAdd(&g_barArrive, 1) == GRID - 1) {
            g_barArrive = 0;
            __threadfence();
            atomicAdd(&g_barGen, 1);
        } else {
            while (*(volatile int*)&g_barGen == gen) __nanosleep(64);
        }
    }
    __syncthreads();
}

__device__ __forceinline__ int edge_idx(const void* ei, size_t pos, int is64) {
    return is64 ? (int)((const long long*)ei)[pos] : ((const int*)ei)[pos];
}

__global__ void __launch_bounds__(BLK, 4)
k_gcn(const float* __restrict__ x, const void* __restrict__ ei,
      const float* __restrict__ ew, const float* __restrict__ W,
      const float* __restrict__ bias, float* __restrict__ out,
      int n, int E) {
    __shared__ __align__(16) float sWt[D * D];      // sWt[k*64+j] = W[j][k]
    __shared__ __align__(16) float sxT[D * XPAD];   // sxT[k*XPAD+r] = x[row0+r][k]
    __shared__ int sm[BLK / 32];

    const int tid = threadIdx.x;
    const int bid = blockIdx.x;
    const int gt  = bid * BLK + tid;
    const int nb  = (n + BLK - 1) / BLK;
    const int lane = tid & 31;
    const int wid  = tid >> 5;

    // ---- P1: init deg=1 / cnt=0 ; block 0 sniffs edge_index dtype ----
    for (int i = gt; i < n; i += GRID * BLK) { g_deg[i] = 1.0f; g_cnt[i] = 0; }
    if (bid == 0) {
        if (tid == 0) sm[0] = 1;
        __syncthreads();
        const long long* p = (const long long*)ei;
        int scan = 2 * E < 2048 ? 2 * E : 2048;
        for (int t = tid; t < scan; t += BLK) {
            long long v = p[t];
            if (v < 0 || v >= (long long)n) sm[0] = 0;   // benign race
        }
        __syncthreads();
        if (tid == 0) g_is64 = sm[0];
    }
    gbar();

    // ---- P2: edge deg/cnt atomics + register-tiled GEMM ----
    {
        const int is64 = g_is64;
        for (int e = gt; e < E; e += GRID * BLK) {
            int r = edge_idx(ei, e, is64);
            if ((unsigned)r < (unsigned)n) {
                atomicAdd(&g_deg[r], ew[e]);
                atomicAdd(&g_cnt[r], 1);
            }
        }
        // stage W transposed (once per block)
        for (int i = tid; i < D * D; i += BLK) {
            int j = i >> 6, k = i & 63;
            sWt[k * D + j] = W[i];
        }
        // 64x64 tile per block iter; 16x16 threads, 4x4 outputs per thread
        const int tx = tid & 15, ty = tid >> 4;
        int ntiles = (n + 63) / 64;
        for (int t = bid; t < ntiles; t += GRID) {
            int row0 = t * 64;
            __syncthreads();
            // load x tile transposed: idx -> r = idx>>6 (row), k = idx&63
            #pragma unroll
            for (int m = 0; m < 16; m++) {
                int idx = tid + m * BLK;
                int r = idx >> 6, k = idx & 63;
                int gr = row0 + r;
                sxT[k * XPAD + r] = (gr < n) ? x[(size_t)gr * D + k] : 0.0f;
            }
            __syncthreads();
            float acc[4][4] = {};
            #pragma unroll 8
            for (int k = 0; k < D; k++) {
                float4 a = *(const float4*)&sxT[k * XPAD + ty * 4];
                float4 b = *(const float4*)&sWt[k * D + tx * 4];
                acc[0][0] = fmaf(a.x, b.x, acc[0][0]);
                acc[0][1] = fmaf(a.x, b.y, acc[0][1]);
                acc[0][2] = fmaf(a.x, b.z, acc[0][2]);
                acc[0][3] = fmaf(a.x, b.w, acc[0][3]);
                acc[1][0] = fmaf(a.y, b.x, acc[1][0]);
                acc[1][1] = fmaf(a.y, b.y, acc[1][1]);
                acc[1][2] = fmaf(a.y, b.z, acc[1][2]);
                acc[1][3] = fmaf(a.y, b.w, acc[1][3]);
                acc[2][0] = fmaf(a.z, b.x, acc[2][0]);
                acc[2][1] = fmaf(a.z, b.y, acc[2][1]);
                acc[2][2] = fmaf(a.z, b.z, acc[2][2]);
                acc[2][3] = fmaf(a.z, b.w, acc[2][3]);
                acc[3][0] = fmaf(a.w, b.x, acc[3][0]);
                acc[3][1] = fmaf(a.w, b.y, acc[3][1]);
                acc[3][2] = fmaf(a.w, b.z, acc[3][2]);
                acc[3][3] = fmaf(a.w, b.w, acc[3][3]);
            }
            #pragma unroll
            for (int i = 0; i < 4; i++) {
                int gr = row0 + ty * 4 + i;
                if (gr < n) {
                    float4 v = make_float4(acc[i][0], acc[i][1], acc[i][2], acc[i][3]);
                    *(float4*)&g_y[(size_t)gr * D + tx * 4] = v;
                }
            }
        }
    }
    gbar();

    // ---- P3: dis = rsqrt(deg) + block-local scan of cnt (warp shuffles) ----
    int local_excl = 0;
    if (bid < nb) {
        int i = bid * BLK + tid;
        int myc = (i < n) ? g_cnt[i] : 0;
        if (i < n) g_dis[i] = rsqrtf(g_deg[i]);
        // warp inclusive scan
        int v = myc;
        #pragma unroll
        for (int off = 1; off < 32; off <<= 1) {
            int u = __shfl_up_sync(0xFFFFFFFF, v, off);
            if (lane >= off) v += u;
        }
        if (lane == 31) sm[wid] = v;
        __syncthreads();
        if (wid == 0) {
            int w = (lane < BLK / 32) ? sm[lane] : 0;
            #pragma unroll
            for (int off = 1; off < BLK / 32; off <<= 1) {
                int u = __shfl_up_sync(0xFFFFFFFF, w, off);
                if (lane >= off) w += u;
            }
            if (lane < BLK / 32) sm[lane] = w;
        }
        __syncthreads();
        int warp_base = (wid == 0) ? 0 : sm[wid - 1];
        local_excl = warp_base + v - myc;    // exclusive, stays in reg across gbar
        if (tid == BLK - 1) g_bsum[bid] = warp_base + v;
    }
    gbar();

    // ---- P4: cross-block exclusive offset + write base/pos ----
    if (bid < nb) {
        int acc = 0;
        for (int t = tid; t < bid; t += BLK) acc += g_bsum[t];
        #pragma unroll
        for (int off = 16; off > 0; off >>= 1)
            acc += __shfl_down_sync(0xFFFFFFFF, acc, off);
        if (lane == 0) sm[wid] = acc;
        __syncthreads();
        if (wid == 0) {
            int w = (lane < BLK / 32) ? sm[lane] : 0;
            #pragma unroll
            for (int off = 4; off > 0; off >>= 1)
                w += __shfl_down_sync(0xFFFFFFFF, w, off);
            if (lane == 0) sm[0] = w;
        }
        __syncthreads();
        int off = sm[0];
        int i = bid * BLK + tid;
        if (i < n) {
            int b = off + local_excl;
            g_base[i] = b;
            g_pos[i]  = b;
        }
    }
    gbar();

    // ---- P5: reorder edges into CSR: epack[pos[row]++] = (col, norm) ----
    {
        const int is64 = g_is64;
        for (int e = gt; e < E; e += GRID * BLK) {
            int r  = edge_idx(ei, e, is64);
            int cl = edge_idx(ei, (size_t)E + e, is64);
            if ((unsigned)r >= (unsigned)n || (unsigned)cl >= (unsigned)n) continue;
            float nm = g_dis[r] * ew[e] * g_dis[cl];
            int p = atomicAdd(&g_pos[r], 1);
            g_epack[p] = make_float2(__int_as_float(cl), nm);
        }
    }
    gbar();

    // ---- P6: gather, warp per node; lane owns float2 of output row ----
    {
        int gw = gt >> 5;
        int j = lane << 1;
        for (int node = gw; node < n; node += NWARPS) {
            float s = g_dis[node];
            float2 yv = *(const float2*)&g_y[(size_t)node * D + j];
            float a0 = bias[j]     + yv.x * s * s;
            float a1 = bias[j + 1] + yv.y * s * s;
            int p   = g_base[node];
            int end = p + g_cnt[node];
            for (; p + 4 <= end; p += 4) {
                float2 pk0 = g_epack[p];
                float2 pk1 = g_epack[p + 1];
                float2 pk2 = g_epack[p + 2];
                float2 pk3 = g_epack[p + 3];
                const float2 v0 = *(const float2*)&g_y[(size_t)__float_as_int(pk0.x) * D + j];
                const float2 v1 = *(const float2*)&g_y[(size_t)__float_as_int(pk1.x) * D + j];
                const float2 v2 = *(const float2*)&g_y[(size_t)__float_as_int(pk2.x) * D + j];
                const float2 v3 = *(const float2*)&g_y[(size_t)__float_as_int(pk3.x) * D + j];
                a0 = fmaf(v0.x, pk0.y, a0);  a1 = fmaf(v0.y, pk0.y, a1);
                a0 = fmaf(v1.x, pk1.y, a0);  a1 = fmaf(v1.y, pk1.y, a1);
                a0 = fmaf(v2.x, pk2.y, a0);  a1 = fmaf(v2.y, pk2.y, a1);
                a0 = fmaf(v3.x, pk3.y, a0);  a1 = fmaf(v3.y, pk3.y, a1);
            }
            for (; p < end; p++) {
                float2 pk = g_epack[p];
                const float2 v = *(const float2*)&g_y[(size_t)__float_as_int(pk.x) * D + j];
                a0 = fmaf(v.x, pk.y, a0);
                a1 = fmaf(v.y, pk.y, a1);
            }
            *(float2*)&out[(size_t)node * D + j] = make_float2(a0, a1);
        }
    }
}

// ---------------------------------------------------------------------------
extern "C" void kernel_launch(void* const* d_in, const int* in_sizes, int n_in,
                              void* d_out, int out_size) {
    const float* x    = (const float*)d_in[0];   // [N,64] f32
    const void*  ei   = d_in[1];                 // [2,E] i64 or i32
    const float* ew   = (const float*)d_in[2];   // [E]   f32
    const float* W    = (const float*)d_in[3];   // [64,64] f32
    const float* bias = (const float*)d_in[4];   // [64]  f32
    float*       out  = (float*)d_out;           // [N,64] f32

    int N = in_sizes[0] / D;
    int E = in_sizes[1] / 2;
    if (N > MAX_N) N = MAX_N;
    if (E > MAX_E) E = MAX_E;

    k_gcn<<<GRID, BLK>>>(x, ei, ew, W, bias, out, N, E);
}

// round 15
// speedup vs baseline: 1.7881x; 1.1498x over previous
#include <cuda_runtime.h>
#include <cuda_bf16.h>
#include <stdint.h>

#define MAX_N 100000
#define MAX_E 1000000
#define D 64
#define GRID 592          // 148 SMs * 4 CTAs, all co-resident
#define BLK 256
#define NWARPS (GRID * BLK / 32)
#define XPAD 68           // multiple of 4 -> 16B-aligned float4 rows in sxT
#define FIXS 16777216.0f  // 2^24 fixed-point scale for weighted degree

// Scratch (device globals; no allocation allowed)
__device__ unsigned long long g_dc[MAX_N];   // hi: edge count, lo: fixed-point deg
__device__ float g_dis[MAX_N];
__device__ int   g_cnt[MAX_N];
__device__ int   g_base[MAX_N];
__device__ int   g_rank[MAX_E];
__device__ int   g_bsum[(MAX_N + BLK - 1) / BLK];
__device__ __align__(16) float  g_y[(size_t)MAX_N * D];     // y = x @ W^T
__device__ __align__(16) float2 g_epack[MAX_E];             // (col, ew) CSR-ordered
__device__ int g_is64;

// software grid barrier (all GRID blocks resident by construction)
__device__ int g_barArrive = 0;
__device__ int g_barGen    = 0;

__device__ __forceinline__ void gbar() {
    __syncthreads();
    if (threadIdx.x == 0) {
        __threadfence();
        int gen = *(volatile int*)&g_barGen;
        if (atomicAdd(&g_barArrive, 1) == GRID - 1) {
            g_barArrive = 0;
            __threadfence();
            atomicAdd(&g_barGen, 1);
        } else {
            while (*(volatile int*)&g_barGen == gen) __nanosleep(64);
        }
    }
    __syncthreads();
}

__device__ __forceinline__ int edge_idx(const void* ei, size_t pos, int is64) {
    return is64 ? (int)((const long long*)ei)[pos] : ((const int*)ei)[pos];
}

__global__ void __launch_bounds__(BLK, 4)
k_gcn(const float* __restrict__ x, const void* __restrict__ ei,
      const float* __restrict__ ew, const float* __restrict__ W,
      const float* __restrict__ bias, float* __restrict__ out,
      int n, int E) {
    __shared__ __align__(16) float sWt[D * D];      // sWt[k*64+j] = W[j][k]
    __shared__ __align__(16) float sxT[D * XPAD];   // sxT[k*XPAD+r] = x[row0+r][k]
    __shared__ int sm[BLK / 32];

    const int tid = threadIdx.x;
    const int bid = blockIdx.x;
    const int gt  = bid * BLK + tid;
    const int nb  = (n + BLK - 1) / BLK;
    const int lane = tid & 31;
    const int wid  = tid >> 5;

    // ---- P1: init dc=0 ; block 0 sniffs edge_index dtype ----
    for (int i = gt; i < n; i += GRID * BLK) g_dc[i] = 0ULL;
    if (bid == 0) {
        if (tid == 0) sm[0] = 1;
        __syncthreads();
        const long long* p = (const long long*)ei;
        int scan = 2 * E < 2048 ? 2 * E : 2048;
        for (int t = tid; t < scan; t += BLK) {
            long long v = p[t];
            if (v < 0 || v >= (long long)n) sm[0] = 0;   // benign race
        }
        __syncthreads();
        if (tid == 0) g_is64 = sm[0];
    }
    gbar();

    // ---- P2: single packed 64-bit atomic per edge (+rank) + tiled GEMM ----
    {
        const int is64 = g_is64;
        for (int e = gt; e < E; e += GRID * BLK) {
            int r = edge_idx(ei, e, is64);
            if ((unsigned)r < (unsigned)n) {
                unsigned fx = __float2uint_rn(ew[e] * FIXS);
                unsigned long long old =
                    atomicAdd(&g_dc[r], (1ULL << 32) | (unsigned long long)fx);
                g_rank[e] = (int)(old >> 32);
            }
        }
        // stage W transposed (once per block)
        for (int i = tid; i < D * D; i += BLK) {
            int j = i >> 6, k = i & 63;
            sWt[k * D + j] = W[i];
        }
        // 64x64 tile per block iter; 16x16 threads, 4x4 outputs per thread
        const int tx = tid & 15, ty = tid >> 4;
        int ntiles = (n + 63) / 64;
        for (int t = bid; t < ntiles; t += GRID) {
            int row0 = t * 64;
            __syncthreads();
            #pragma unroll
            for (int m = 0; m < 16; m++) {
                int idx = tid + m * BLK;
                int r = idx >> 6, k = idx & 63;
                int gr = row0 + r;
                sxT[k * XPAD + r] = (gr < n) ? x[(size_t)gr * D + k] : 0.0f;
            }
            __syncthreads();
            float acc[4][4] = {};
            #pragma unroll 8
            for (int k = 0; k < D; k++) {
                float4 a = *(const float4*)&sxT[k * XPAD + ty * 4];
                float4 b = *(const float4*)&sWt[k * D + tx * 4];
                acc[0][0] = fmaf(a.x, b.x, acc[0][0]);
                acc[0][1] = fmaf(a.x, b.y, acc[0][1]);
                acc[0][2] = fmaf(a.x, b.z, acc[0][2]);
                acc[0][3] = fmaf(a.x, b.w, acc[0][3]);
                acc[1][0] = fmaf(a.y, b.x, acc[1][0]);
                acc[1][1] = fmaf(a.y, b.y, acc[1][1]);
                acc[1][2] = fmaf(a.y, b.z, acc[1][2]);
                acc[1][3] = fmaf(a.y, b.w, acc[1][3]);
                acc[2][0] = fmaf(a.z, b.x, acc[2][0]);
                acc[2][1] = fmaf(a.z, b.y, acc[2][1]);
                acc[2][2] = fmaf(a.z, b.z, acc[2][2]);
                acc[2][3] = fmaf(a.z, b.w, acc[2][3]);
                acc[3][0] = fmaf(a.w, b.x, acc[3][0]);
                acc[3][1] = fmaf(a.w, b.y, acc[3][1]);
                acc[3][2] = fmaf(a.w, b.z, acc[3][2]);
                acc[3][3] = fmaf(a.w, b.w, acc[3][3]);
            }
            #pragma unroll
            for (int i = 0; i < 4; i++) {
                int gr = row0 + ty * 4 + i;
                if (gr < n) {
                    float4 v = make_float4(acc[i][0], acc[i][1], acc[i][2], acc[i][3]);
                    *(float4*)&g_y[(size_t)gr * D + tx * 4] = v;
                }
            }
        }
    }
    gbar();

    // ---- P3: unpack cnt/deg, dis = rsqrt(deg), block-local scan of cnt ----
    int local_excl = 0;
    if (bid < nb) {
        int i = bid * BLK + tid;
        int myc = 0;
        if (i < n) {
            unsigned long long dc = g_dc[i];
            myc = (int)(dc >> 32);
            float deg = 1.0f + (float)(unsigned)(dc & 0xFFFFFFFFULL) * (1.0f / FIXS);
            g_dis[i] = rsqrtf(deg);
            g_cnt[i] = myc;
        }
        int v = myc;
        #pragma unroll
        for (int off = 1; off < 32; off <<= 1) {
            int u = __shfl_up_sync(0xFFFFFFFF, v, off);
            if (lane >= off) v += u;
        }
        if (lane == 31) sm[wid] = v;
        __syncthreads();
        if (wid == 0) {
            int w = (lane < BLK / 32) ? sm[lane] : 0;
            #pragma unroll
            for (int off = 1; off < BLK / 32; off <<= 1) {
                int u = __shfl_up_sync(0xFFFFFFFF, w, off);
                if (lane >= off) w += u;
            }
            if (lane < BLK / 32) sm[lane] = w;
        }
        __syncthreads();
        int warp_base = (wid == 0) ? 0 : sm[wid - 1];
        local_excl = warp_base + v - myc;    // exclusive, stays in reg across gbar
        if (tid == BLK - 1) g_bsum[bid] = warp_base + v;
    }
    gbar();

    // ---- P4: cross-block exclusive offset + write base ----
    if (bid < nb) {
        int acc = 0;
        for (int t = tid; t < bid; t += BLK) acc += g_bsum[t];
        #pragma unroll
        for (int off = 16; off > 0; off >>= 1)
            acc += __shfl_down_sync(0xFFFFFFFF, acc, off);
        if (lane == 0) sm[wid] = acc;
        __syncthreads();
        if (wid == 0) {
            int w = (lane < BLK / 32) ? sm[lane] : 0;
            #pragma unroll
            for (int off = 4; off > 0; off >>= 1)
                w += __shfl_down_sync(0xFFFFFFFF, w, off);
            if (lane == 0) sm[0] = w;
        }
        __syncthreads();
        int off = sm[0];
        int i = bid * BLK + tid;
        if (i < n) g_base[i] = off + local_excl;
    }
    gbar();

    // ---- P5: reorder (no atomics, no dis): epack[base[r]+rank[e]] = (col, ew) ----
    {
        const int is64 = g_is64;
        for (int e = gt; e < E; e += GRID * BLK) {
            int r  = edge_idx(ei, e, is64);
            int cl = edge_idx(ei, (size_t)E + e, is64);
            if ((unsigned)r >= (unsigned)n || (unsigned)cl >= (unsigned)n) continue;
            int p = g_base[r] + g_rank[e];
            g_epack[p] = make_float2(__int_as_float(cl), ew[e]);
        }
    }
    gbar();

    // ---- P6: gather, warp per node; norm computed here ----
    {
        int gw = gt >> 5;
        int j = lane << 1;
        for (int node = gw; node < n; node += NWARPS) {
            float s = g_dis[node];
            float2 yv = *(const float2*)&g_y[(size_t)node * D + j];
            float a0 = bias[j]     + yv.x * s * s;
            float a1 = bias[j + 1] + yv.y * s * s;
            int p   = g_base[node];
            int end = p + g_cnt[node];
            for (; p + 4 <= end; p += 4) {
                float2 pk0 = g_epack[p];
                float2 pk1 = g_epack[p + 1];
                float2 pk2 = g_epack[p + 2];
                float2 pk3 = g_epack[p + 3];
                int c0 = __float_as_int(pk0.x), c1 = __float_as_int(pk1.x);
                int c2 = __float_as_int(pk2.x), c3 = __float_as_int(pk3.x);
                float n0 = s * pk0.y * g_dis[c0];
                float n1 = s * pk1.y * g_dis[c1];
                float n2 = s * pk2.y * g_dis[c2];
                float n3 = s * pk3.y * g_dis[c3];
                const float2 v0 = *(const float2*)&g_y[(size_t)c0 * D + j];
                const float2 v1 = *(const float2*)&g_y[(size_t)c1 * D + j];
                const float2 v2 = *(const float2*)&g_y[(size_t)c2 * D + j];
                const float2 v3 = *(const float2*)&g_y[(size_t)c3 * D + j];
                a0 = fmaf(v0.x, n0, a0);  a1 = fmaf(v0.y, n0, a1);
                a0 = fmaf(v1.x, n1, a0);  a1 = fmaf(v1.y, n1, a1);
                a0 = fmaf(v2.x, n2, a0);  a1 = fmaf(v2.y, n2, a1);
                a0 = fmaf(v3.x, n3, a0);  a1 = fmaf(v3.y, n3, a1);
            }
            for (; p < end; p++) {
                float2 pk = g_epack[p];
                int c = __float_as_int(pk.x);
                float nm = s * pk.y * g_dis[c];
                const float2 v = *(const float2*)&g_y[(size_t)c * D + j];
                a0 = fmaf(v.x, nm, a0);
                a1 = fmaf(v.y, nm, a1);
            }
            *(float2*)&out[(size_t)node * D + j] = make_float2(a0, a1);
        }
    }
}

// ---------------------------------------------------------------------------
extern "C" void kernel_launch(void* const* d_in, const int* in_sizes, int n_in,
                              void* d_out, int out_size) {
    const float* x    = (const float*)d_in[0];   // [N,64] f32
    const void*  ei   = d_in[1];                 // [2,E] i64 or i32
    const float* ew   = (const float*)d_in[2];   // [E]   f32
    const float* W    = (const float*)d_in[3];   // [64,64] f32
    const float* bias = (const float*)d_in[4];   // [64]  f32
    float*       out  = (float*)d_out;           // [N,64] f32

    int N = in_sizes[0] / D;
    int E = in_sizes[1] / 2;
    if (N > MAX_N) N = MAX_N;
    if (E > MAX_E) E = MAX_E;

    k_gcn<<<GRID, BLK>>>(x, ei, ew, W, bias, out, N, E);
}